// round 6
// baseline (speedup 1.0000x reference)
#include <cuda_runtime.h>

// Problem constants (B=32, T=1024, N=2048)
#define BB 32
#define TT 1024
#define NN 2048
#define ALPHA 0.995f
#define VTH   2.0f

// Scratch (device globals -- no allocation allowed)
__device__ float g_S[BB * TT];   // S[b][t] = x[b,t,:] . w
__device__ float g_A[BB * TT];   // a[b][t] = v_t + q_t
__device__ float g_V2[BB];       // sum of v_t^2 per batch

// ---------------------------------------------------------------------------
// Kernel 1: S[b,t] = x[b,t,:] . w   (row dot products), [b][t] layout.
// grid = 4096 CTAs x 8 rows each, block = 128 threads, float4 loads.
// Measured ~6.15 TB/s -- at the read-stream HBM ceiling, unchanged.
// ---------------------------------------------------------------------------
__global__ __launch_bounds__(128) void k_gemv(const float4* __restrict__ X4,
                                              const float4* __restrict__ W4) {
    __shared__ float red[4];
    const int tid = threadIdx.x;

    const float4 w0 = W4[tid];
    const float4 w1 = W4[128 + tid];
    const float4 w2 = W4[256 + tid];
    const float4 w3 = W4[384 + tid];

    const int base_row = blockIdx.x * 8;

#pragma unroll 1
    for (int rr = 0; rr < 8; rr++) {
        const int r = base_row + rr;                 // r = b*TT + t
        const float4* xp = X4 + (size_t)r * (NN / 4);
        const float4 x0 = xp[tid];
        const float4 x1 = xp[128 + tid];
        const float4 x2 = xp[256 + tid];
        const float4 x3 = xp[384 + tid];

        float s = x0.x * w0.x + x0.y * w0.y + x0.z * w0.z + x0.w * w0.w
                + x1.x * w1.x + x1.y * w1.y + x1.z * w1.z + x1.w * w1.w
                + x2.x * w2.x + x2.y * w2.y + x2.z * w2.z + x2.w * w2.w
                + x3.x * w3.x + x3.y * w3.y + x3.z * w3.z + x3.w * w3.w;

#pragma unroll
        for (int o = 16; o > 0; o >>= 1)
            s += __shfl_xor_sync(0xFFFFFFFFu, s, o);
        if ((tid & 31) == 0) red[tid >> 5] = s;
        __syncthreads();
        if (tid == 0) g_S[r] = red[0] + red[1] + red[2] + red[3];
        __syncthreads();
    }
}

// ---------------------------------------------------------------------------
// Kernel 2: per-batch scalar scans, one CTA per batch, scan from SMEM.
// Forward chain uses pred-as-data select (FSETP->FSEL->FADD ~12cy/iter)
// instead of an @P-guarded add (13cy pred-as-guard).
// ---------------------------------------------------------------------------
__global__ __launch_bounds__(128) void k_scan(const float* __restrict__ w,
                                              float* __restrict__ out) {
    __shared__ float sv[TT];   // holds s, then v in place
    __shared__ float sa[TT];   // a_t
    __shared__ float s_ww;
    const int tid = threadIdx.x;
    const int b   = blockIdx.x;

    const float* srow = g_S + b * TT;
    for (int t = tid; t < TT; t += 128) sv[t] = srow[t];

    if (tid < 32) {
        float ww = 0.0f;
#pragma unroll 8
        for (int i = tid; i < NN; i += 32) ww += w[i] * w[i];
#pragma unroll
        for (int o = 16; o > 0; o >>= 1)
            ww += __shfl_xor_sync(0xFFFFFFFFu, ww, o);
        if (tid == 0) s_ww = ww;
    }
    __syncthreads();

    if (tid == 0) {
        const float ww = s_ww;

        // ---- forward scan: v_t = a*v_{t-1} + s_t - VTH*z_{t-1} ----
        float v = 0.0f, v2 = 0.0f;
#pragma unroll 8
        for (int t = 0; t < TT; t++) {
            const float s   = sv[t];
            const float sub = (v > VTH) ? VTH : 0.0f;  // pred-as-data FSEL
            v = fmaf(ALPHA, v, s) - sub;
            sv[t] = v;
            v2 += v * v;                               // off-chain
        }
        g_V2[b] = v2;

        // ---- backward scan: c_t reconstructed from v values ----
        float q = 0.0f;
#pragma unroll 8
        for (int t = TT - 1; t > 0; t--) {
            const float vt = sv[t];
            const float vp = sv[t - 1];
            sa[t] = vt + q;                                  // a_t = v_t + q_t
            const float zc = (vp > VTH) ? VTH : 0.0f;
            const float c  = vt - ALPHA * vp - vt * ww + zc; // off-chain
            q = fmaf(ALPHA, q, c);                           // 4cy chain
        }
        sa[0] = sv[0] + q;
    }
    __syncthreads();

    float* vout = out + b * TT;
    float* zout = out + BB * TT + b * TT;
    float* aout = g_A + b * TT;
    for (int t = tid; t < TT; t += 128) {
        const float v = sv[t];
        vout[t] = v;
        zout[t] = (v > VTH) ? 1.0f : 0.0f;
        aout[t] = sa[t];
    }
}

// ---------------------------------------------------------------------------
// Kernel 3 (fused): grad[b,n] = sum_t a[b,t]*x[b,t,n] - V2[b]*w[n]
// grid = (16 column-chunks, 32 batches) = 512 CTAs, block = 128.
// Each warp takes a T-quarter of the SAME 32 float4-columns; smem reduce.
// ---------------------------------------------------------------------------
__global__ __launch_bounds__(128) void k_grad(const float4* __restrict__ X4,
                                              const float4* __restrict__ W4,
                                              float* __restrict__ out) {
    __shared__ float  sa[TT];
    __shared__ float4 part[4][32];
    const int tid    = threadIdx.x;
    const int lane   = tid & 31;
    const int tslice = tid >> 5;     // warp id = T-quarter
    const int chunk  = blockIdx.x;   // 0..15
    const int b      = blockIdx.y;   // 0..31

    for (int t = tid; t < TT; t += 128) sa[t] = g_A[b * TT + t];
    __syncthreads();

    const int col4 = chunk * 32 + lane;            // float4 column, 0..511
    const int t0   = tslice * (TT / 4);
    const float4* xp = X4 + ((size_t)b * TT + t0) * (NN / 4) + col4;

    float4 acc = make_float4(0.f, 0.f, 0.f, 0.f);
#pragma unroll 8
    for (int t = 0; t < TT / 4; t++) {
        const float a = sa[t0 + t];
        const float4 x = xp[(size_t)t * (NN / 4)];
        acc.x += a * x.x;
        acc.y += a * x.y;
        acc.z += a * x.z;
        acc.w += a * x.w;
    }
    part[tslice][lane] = acc;
    __syncthreads();

    if (tslice == 0) {
        const float4 p1 = part[1][lane];
        const float4 p2 = part[2][lane];
        const float4 p3 = part[3][lane];
        acc.x += p1.x + p2.x + p3.x;
        acc.y += p1.y + p2.y + p3.y;
        acc.z += p1.z + p2.z + p3.z;
        acc.w += p1.w + p2.w + p3.w;

        const float v2 = g_V2[b];
        const float4 wv = W4[col4];
        float4 g;
        g.x = acc.x - v2 * wv.x;
        g.y = acc.y - v2 * wv.y;
        g.z = acc.z - v2 * wv.z;
        g.w = acc.w - v2 * wv.w;

        float4* gout = (float4*)(out + 2 * BB * TT);
        gout[(size_t)b * (NN / 4) + col4] = g;
    }
}

// ---------------------------------------------------------------------------
extern "C" void kernel_launch(void* const* d_in, const int* in_sizes, int n_in,
                              void* d_out, int out_size) {
    const float* x = (const float*)d_in[0];
    const float* w = (const float*)d_in[1];
    if (n_in >= 2 && in_sizes[0] == NN && in_sizes[1] != NN) {
        const float* tmp = x; x = w; w = tmp;
    }
    float* out = (float*)d_out;

    k_gemv<<<4096, 128>>>((const float4*)x, (const float4*)w);
    k_scan<<<32, 128>>>(w, out);
    k_grad<<<dim3(16, 32), 128>>>((const float4*)x, (const float4*)w, out);
}

// round 7
// speedup vs baseline: 1.2058x; 1.2058x over previous
#include <cuda_runtime.h>

// Problem constants (B=32, T=1024, N=2048)
#define BB 32
#define TT 1024
#define NN 2048
#define ALPHA 0.995f
#define VTH   2.0f
#define SEG   16          // T-segments for k_grad_partial
#define TSEG  (TT / SEG)  // 64 timesteps per segment

// Scratch (device globals -- no allocation allowed)
__device__ float g_S[BB * TT];   // S[b][t] = x[b,t,:] . w
__device__ float g_A[BB * TT];   // a[b][t] = v_t + q_t
__device__ float g_V2[BB];       // sum of v_t^2 per batch

// ---------------------------------------------------------------------------
// Kernel 1: S[b,t] = x[b,t,:] . w   (row dot products), [b][t] layout.
// grid = 4096 CTAs x 8 rows each, block = 128 threads, float4 loads.
// Measured ~6.15 TB/s -- at the read-stream HBM ceiling, unchanged.
// ---------------------------------------------------------------------------
__global__ __launch_bounds__(128) void k_gemv(const float4* __restrict__ X4,
                                              const float4* __restrict__ W4) {
    __shared__ float red[4];
    const int tid = threadIdx.x;

    const float4 w0 = W4[tid];
    const float4 w1 = W4[128 + tid];
    const float4 w2 = W4[256 + tid];
    const float4 w3 = W4[384 + tid];

    const int base_row = blockIdx.x * 8;

#pragma unroll 1
    for (int rr = 0; rr < 8; rr++) {
        const int r = base_row + rr;                 // r = b*TT + t
        const float4* xp = X4 + (size_t)r * (NN / 4);
        const float4 x0 = xp[tid];
        const float4 x1 = xp[128 + tid];
        const float4 x2 = xp[256 + tid];
        const float4 x3 = xp[384 + tid];

        float s = x0.x * w0.x + x0.y * w0.y + x0.z * w0.z + x0.w * w0.w
                + x1.x * w1.x + x1.y * w1.y + x1.z * w1.z + x1.w * w1.w
                + x2.x * w2.x + x2.y * w2.y + x2.z * w2.z + x2.w * w2.w
                + x3.x * w3.x + x3.y * w3.y + x3.z * w3.z + x3.w * w3.w;

#pragma unroll
        for (int o = 16; o > 0; o >>= 1)
            s += __shfl_xor_sync(0xFFFFFFFFu, s, o);
        if ((tid & 31) == 0) red[tid >> 5] = s;
        __syncthreads();
        if (tid == 0) g_S[r] = red[0] + red[1] + red[2] + red[3];
        __syncthreads();
    }
}

// ---------------------------------------------------------------------------
// Kernel 2: per-batch scalar scans, one CTA per batch, scan from SMEM.
// Also zeroes the grad region of d_out (atomic targets for k_grad_partial).
// ---------------------------------------------------------------------------
__global__ __launch_bounds__(128) void k_scan(const float* __restrict__ w,
                                              float* __restrict__ out) {
    __shared__ float sv[TT];   // holds s, then v in place
    __shared__ float sa[TT];   // a_t
    __shared__ float s_ww;
    const int tid = threadIdx.x;
    const int b   = blockIdx.x;

    const float* srow = g_S + b * TT;
    for (int t = tid; t < TT; t += 128) sv[t] = srow[t];

    // zero this batch's grad slice (coalesced float4 stores)
    {
        float4* gz = (float4*)(out + 2 * BB * TT + b * NN);
#pragma unroll
        for (int i = tid; i < NN / 4; i += 128)
            gz[i] = make_float4(0.f, 0.f, 0.f, 0.f);
    }

    if (tid < 32) {
        float ww = 0.0f;
#pragma unroll 8
        for (int i = tid; i < NN; i += 32) ww += w[i] * w[i];
#pragma unroll
        for (int o = 16; o > 0; o >>= 1)
            ww += __shfl_xor_sync(0xFFFFFFFFu, ww, o);
        if (tid == 0) s_ww = ww;
    }
    __syncthreads();

    if (tid == 0) {
        const float ww = s_ww;

        // ---- forward scan: v_t = a*v_{t-1} + s_t - VTH*z_{t-1} ----
        float v = 0.0f, v2 = 0.0f;
#pragma unroll 8
        for (int t = 0; t < TT; t++) {
            const float s   = sv[t];
            const float sub = (v > VTH) ? VTH : 0.0f;  // pred-as-data FSEL
            v = fmaf(ALPHA, v, s) - sub;
            sv[t] = v;
            v2 += v * v;                               // off-chain
        }
        g_V2[b] = v2;

        // ---- backward scan: c_t reconstructed from v values ----
        float q = 0.0f;
#pragma unroll 8
        for (int t = TT - 1; t > 0; t--) {
            const float vt = sv[t];
            const float vp = sv[t - 1];
            sa[t] = vt + q;                                  // a_t = v_t + q_t
            const float zc = (vp > VTH) ? VTH : 0.0f;
            const float c  = vt - ALPHA * vp - vt * ww + zc; // off-chain
            q = fmaf(ALPHA, q, c);                           // 4cy FFMA chain
        }
        sa[0] = sv[0] + q;
    }
    __syncthreads();

    float* vout = out + b * TT;
    float* zout = out + BB * TT + b * TT;
    float* aout = g_A + b * TT;
    for (int t = tid; t < TT; t += 128) {
        const float v = sv[t];
        vout[t] = v;
        zout[t] = (v > VTH) ? 1.0f : 0.0f;
        aout[t] = sa[t];
    }
}

// ---------------------------------------------------------------------------
// Kernel 3: partial grad over a T-segment, accumulated into d_out via RED.
//   grad[b][n] += sum_{t in seg} a[b,t] * x[b,t,n]   (- V2[b]*w[n] on seg 0)
// grid = (4 chunks, 32 b, SEG) = 2048 CTAs, block = 128 threads.
// Per-row footprint per CTA: 128 threads x 16B = 2048 B contiguous (the
// shape measured at ~5.9 TB/s in R4 -- do NOT narrow it).
// ---------------------------------------------------------------------------
__global__ __launch_bounds__(128) void k_grad_partial(const float4* __restrict__ X4,
                                                      const float4* __restrict__ W4,
                                                      float* __restrict__ out) {
    __shared__ float sa[TSEG];
    const int tid   = threadIdx.x;   // 0..127
    const int chunk = blockIdx.x;    // 0..3
    const int b     = blockIdx.y;    // 0..31
    const int seg   = blockIdx.z;    // 0..SEG-1
    const int t0    = seg * TSEG;

    if (tid < TSEG) sa[tid] = g_A[b * TT + t0 + tid];
    __syncthreads();

    const int col4 = chunk * 128 + tid;  // float4 column index, 0..511
    const float4* xp = X4 + ((size_t)b * TT + t0) * (NN / 4) + col4;

    float4 acc = make_float4(0.f, 0.f, 0.f, 0.f);
#pragma unroll 8
    for (int t = 0; t < TSEG; t++) {
        const float a = sa[t];
        const float4 x = xp[(size_t)t * (NN / 4)];
        acc.x += a * x.x;
        acc.y += a * x.y;
        acc.z += a * x.z;
        acc.w += a * x.w;
    }

    if (seg == 0) {  // fold in -V2[b]*w[n] exactly once
        const float v2 = g_V2[b];
        const float4 wv = W4[col4];
        acc.x -= v2 * wv.x;
        acc.y -= v2 * wv.y;
        acc.z -= v2 * wv.z;
        acc.w -= v2 * wv.w;
    }

    float* gout = out + 2 * BB * TT + b * NN + col4 * 4;
    atomicAdd(gout + 0, acc.x);   // RED.E.ADD.F32 (no return)
    atomicAdd(gout + 1, acc.y);
    atomicAdd(gout + 2, acc.z);
    atomicAdd(gout + 3, acc.w);
}

// ---------------------------------------------------------------------------
extern "C" void kernel_launch(void* const* d_in, const int* in_sizes, int n_in,
                              void* d_out, int out_size) {
    const float* x = (const float*)d_in[0];
    const float* w = (const float*)d_in[1];
    if (n_in >= 2 && in_sizes[0] == NN && in_sizes[1] != NN) {
        const float* tmp = x; x = w; w = tmp;
    }
    float* out = (float*)d_out;

    k_gemv<<<4096, 128>>>((const float4*)x, (const float4*)w);
    k_scan<<<32, 128>>>(w, out);
    k_grad_partial<<<dim3(4, 32, SEG), 128>>>((const float4*)x, (const float4*)w, out);
}